// round 10
// baseline (speedup 1.0000x reference)
#include <cuda_runtime.h>

namespace {

constexpr int H  = 64;
constexpr int Fd = 8;
constexpr int Tn = 512;
constexpr int Pn = 64;
constexpr int NT = 256;
constexpr int NBMAX = 4;
constexpr int HP  = 72;     // h row stride
constexpr int SGS = 260;    // sg row stride (floats, 16B aligned)

using u64 = unsigned long long;

__device__ __forceinline__ u64 ffma2(u64 a, u64 b, u64 c) {
    u64 d;
    asm("fma.rn.f32x2 %0, %1, %2, %3;" : "=l"(d) : "l"(a), "l"(b), "l"(c));
    return d;
}
__device__ __forceinline__ float hsum2(u64 v) {
    float lo, hi;
    asm("mov.b64 {%0, %1}, %2;" : "=f"(lo), "=f"(hi) : "l"(v));
    return lo + hi;
}
__device__ __forceinline__ float tanh_a(float x) {
    float y;
    asm("tanh.approx.f32 %0, %1;" : "=f"(y) : "f"(x));
    return y;
}
__device__ __forceinline__ float sig_a(float x) {
    return fmaf(tanh_a(0.5f * x), 0.5f, 0.5f);
}

// Per-thread weights: 4 gate rows of unit U, k-quarter q (chunk-rotated).
struct WReg {
    u64  wh[4][8];
    u64  wx[4];
    float bi[4];
};

__device__ __forceinline__ void load_w(
    const float* __restrict__ Whh, const float* __restrict__ Wih,
    const float* __restrict__ bih, const float* __restrict__ bhh,
    int U, int q, WReg& W)
{
#pragma unroll
    for (int g = 0; g < 4; g++) {
        const int row = 64 * g + U;
        const float* base = Whh + row * H + 16 * q;
#pragma unroll
        for (int c = 0; c < 4; c++) {
            const int cc = (c + q) & 3;
            ulonglong2 v = __ldg((const ulonglong2*)(base + 4 * cc));
            W.wh[g][2 * c]     = v.x;
            W.wh[g][2 * c + 1] = v.y;
        }
        W.wx[g] = __ldg((const u64*)(Wih + row * Fd) + q);
        W.bi[g] = bih[row] + bhh[row];
    }
}

// Gate partials for NBR rows of one set; h rows given by base pointer.
template<int NBR>
__device__ __forceinline__ void gate_set(
    const WReg& W, const float (*__restrict__ h)[HP],
    const u64* __restrict__ xv, float* __restrict__ sgq, int U, int q)
{
#pragma unroll
    for (int b = 0; b < NBR; b++) {
        u64 a0 = 0, a1 = 0, a2 = 0, a3 = 0;
        const u64 x = xv[b];
        a0 = ffma2(W.wx[0], x, a0);
        a1 = ffma2(W.wx[1], x, a1);
        a2 = ffma2(W.wx[2], x, a2);
        a3 = ffma2(W.wx[3], x, a3);
        const float* hb = &h[b][16 * q];
#pragma unroll
        for (int c = 0; c < 4; c++) {
            const int cc = (c + q) & 3;
            ulonglong2 hv = *(const ulonglong2*)(hb + 4 * cc);
            a0 = ffma2(W.wh[0][2 * c], hv.x, a0);
            a1 = ffma2(W.wh[1][2 * c], hv.x, a1);
            a2 = ffma2(W.wh[2][2 * c], hv.x, a2);
            a3 = ffma2(W.wh[3][2 * c], hv.x, a3);
            a0 = ffma2(W.wh[0][2 * c + 1], hv.y, a0);
            a1 = ffma2(W.wh[1][2 * c + 1], hv.y, a1);
            a2 = ffma2(W.wh[2][2 * c + 1], hv.y, a2);
            a3 = ffma2(W.wh[3][2 * c + 1], hv.y, a3);
        }
        *(float4*)&sgq[b * SGS + U * 4] =
            make_float4(hsum2(a0), hsum2(a1), hsum2(a2), hsum2(a3));
    }
}

// Activation for (unit U, set-local row r): sum 4 quarter partials + bias.
__device__ __forceinline__ void act_row(
    const float* __restrict__ sg, int QS, const WReg& W,
    int r, float* __restrict__ hdst, int U, float& c)
{
    const int base = r * SGS + U * 4;
    float4 s0 = *(const float4*)&sg[0 * QS + base];
    float4 s1 = *(const float4*)&sg[1 * QS + base];
    float4 s2 = *(const float4*)&sg[2 * QS + base];
    float4 s3 = *(const float4*)&sg[3 * QS + base];
    float gi = s0.x + s1.x + s2.x + s3.x + W.bi[0];
    float gf = s0.y + s1.y + s2.y + s3.y + W.bi[1];
    float gg = s0.z + s1.z + s2.z + s3.z + W.bi[2];
    float go = s0.w + s1.w + s2.w + s3.w + W.bi[3];
    c = sig_a(gf) * c + sig_a(gi) * tanh_a(gg);
    hdst[U] = sig_a(go) * tanh_a(c);
}

template<int NBA, int NBB>
__device__ __forceinline__ void run_lstm(
    int b0,
    const float* __restrict__ input,
    const float* __restrict__ eWih, const float* __restrict__ eWhh,
    const float* __restrict__ ebih, const float* __restrict__ ebhh,
    const float* __restrict__ dWih, const float* __restrict__ dWhh,
    const float* __restrict__ dbih, const float* __restrict__ dbhh,
    const float* __restrict__ fcW,  const float* __restrict__ fcb,
    float* __restrict__ out,
    float (*__restrict__ hbuf)[NBMAX][HP],   // [2][4][HP]
    float* __restrict__ sgA, float* __restrict__ sgB,
    float (*__restrict__ sx)[Fd],
    float (*__restrict__ sfcW)[H], float* __restrict__ sfcb)
{
    constexpr int NB  = NBA + NBB;
    constexpr int QSA = NBA * SGS;
    constexpr int QSB = NBB * SGS;

    const int tid  = threadIdx.x;
    const int lane = tid & 31;
    const int wrp  = tid >> 5;
    const int q    = wrp & 3;            // k-quarter (warp-uniform); act row
    const int hh   = wrp >> 2;
    const int U    = 32 * hh + lane;     // unit (0..63)

    ((float*)sfcW)[tid]      = fcW[tid];
    ((float*)sfcW)[tid + NT] = fcW[tid + NT];
    if (tid < Fd) sfcb[tid] = fcb[tid];

    if (q < NB) hbuf[0][q][U] = 0.0f;
    float c = 0.0f;

    WReg W;
    load_w(eWhh, eWih, ebih, ebhh, U, q, W);

    // x pointers: q-th u64 (feats 2q,2q+1) of each owned row; warp-uniform.
    const u64* xpA[NBA];
    const u64* xpB[NBB];
#pragma unroll
    for (int b = 0; b < NBA; b++)
        xpA[b] = (const u64*)(input + (size_t)(b0 + b) * Tn * Fd) + q;
#pragma unroll
    for (int b = 0; b < NBB; b++)
        xpB[b] = (const u64*)(input + (size_t)(b0 + NBA + b) * Tn * Fd) + q;

    u64 xA[NBA], xB[NBB], xnA[NBA], xnB[NBB];
#pragma unroll
    for (int b = 0; b < NBA; b++) xA[b] = __ldg(xpA[b]);
#pragma unroll
    for (int b = 0; b < NBB; b++) xB[b] = __ldg(xpB[b]);

    __syncthreads();                     // zeros + fcW visible
    gate_set<NBA>(W, hbuf[0], xA, sgA + q * QSA, U, q);   // A partials, t=0
    __syncthreads();                     // sgA visible

    // ====== encoder: two phase-shifted sets, 2 plain barriers/step ======
    for (int t = 0; t < Tn; t++) {
        const int cur = t & 1, nxt = cur ^ 1;
        if (t + 1 < Tn) {
#pragma unroll
            for (int b = 0; b < NBA; b++) xnA[b] = __ldg(xpA[b] + (size_t)(t + 1) * 4);
#pragma unroll
            for (int b = 0; b < NBB; b++) xnB[b] = __ldg(xpB[b] + (size_t)(t + 1) * 4);
        }

        if (q < NBA) act_row(sgA, QSA, W, q, hbuf[nxt][q], U, c);        // MUFU half
        gate_set<NBB>(W, hbuf[cur] + NBA, xB, sgB + q * QSB, U, q);      // FMA all
        __syncthreads();   // sgB + h_A(t) visible

        if (q >= NBA && q < NB) act_row(sgB, QSB, W, q - NBA, hbuf[nxt][q], U, c);
        if (t + 1 < Tn) {
            gate_set<NBA>(W, hbuf[nxt], xnA, sgA + q * QSA, U, q);
#pragma unroll
            for (int b = 0; b < NBB; b++) xB[b] = xnB[b];
        }
        __syncthreads();   // sgA + h_B(t) visible
    }
    // Tn even: all 4 rows' final h at parity 0.

    // ====== decoder ======
    load_w(dWhh, dWih, dbih, dbhh, U, q, W);

    const bool xth = tid < NB * Fd;
    const int  xb  = tid >> 3;
    const int  xf  = tid & 7;
    if (xth)
        sx[xb][xf] = __ldg(input + ((size_t)(b0 + xb) * Tn + (Tn - 1)) * Fd + xf);

    int cur = 0;
    for (int p = 0; p < Pn; p++) {
        __syncthreads();   // h(parity cur) + sx visible
        u64 xa[NBA], xbv[NBB];
#pragma unroll
        for (int b = 0; b < NBA; b++) xa[b]  = *(const u64*)&sx[b][2 * q];
#pragma unroll
        for (int b = 0; b < NBB; b++) xbv[b] = *(const u64*)&sx[NBA + b][2 * q];

        gate_set<NBA>(W, hbuf[cur], xa, sgA + q * QSA, U, q);
        gate_set<NBB>(W, hbuf[cur] + NBA, xbv, sgB + q * QSB, U, q);
        __syncthreads();   // partials ready

        if (q < NBA)            act_row(sgA, QSA, W, q,       hbuf[cur ^ 1][q], U, c);
        else if (q < NB)        act_row(sgB, QSB, W, q - NBA, hbuf[cur ^ 1][q], U, c);
        __syncthreads();   // h_new ready

        if (xth) {         // pred = h_new @ fcW^T + fcb
            float a = sfcb[xf];
            const float4* hr = (const float4*)&hbuf[cur ^ 1][xb][0];
            const float4* wr = (const float4*)&sfcW[xf][0];
#pragma unroll
            for (int k = 0; k < 16; k++) {
                float4 hv = hr[k], wv = wr[k];
                a = fmaf(hv.x, wv.x, a);
                a = fmaf(hv.y, wv.y, a);
                a = fmaf(hv.z, wv.z, a);
                a = fmaf(hv.w, wv.w, a);
            }
            out[((size_t)(b0 + xb) * Pn + p) * Fd + xf] = a;
            sx[xb][xf] = a;
        }
        cur ^= 1;
        // loop-top barrier orders sx/h for next step
    }
}

__global__ void __launch_bounds__(NT, 2)
seq2seq_lstm_kernel(
    const float* __restrict__ input,
    const float* __restrict__ eWih, const float* __restrict__ eWhh,
    const float* __restrict__ ebih, const float* __restrict__ ebhh,
    const float* __restrict__ dWih, const float* __restrict__ dWhh,
    const float* __restrict__ dbih, const float* __restrict__ dbhh,
    const float* __restrict__ fcW,  const float* __restrict__ fcb,
    float* __restrict__ out)
{
    __shared__ float hbuf[2][NBMAX][HP];
    __shared__ float sgA[4 * 2 * SGS];
    __shared__ float sgB[4 * 2 * SGS];
    __shared__ float sx[NBMAX][Fd];
    __shared__ float sfcW[Fd][H];
    __shared__ float sfcb[Fd];

    const int bid = blockIdx.x;
    if (bid < 136) {
        run_lstm<2, 2>(4 * bid, input, eWih, eWhh, ebih, ebhh,
                       dWih, dWhh, dbih, dbhh, fcW, fcb, out,
                       hbuf, sgA, sgB, sx, sfcW, sfcb);
    } else {
        int b0 = (bid < 148) ? (544 + 3 * (bid - 136))
                             : (580 + 3 * (bid - 148));
        run_lstm<2, 1>(b0, input, eWih, eWhh, ebih, ebhh,
                       dWih, dWhh, dbih, dbhh, fcW, fcb, out,
                       hbuf, sgA, sgB, sx, sfcW, sfcb);
    }
}

} // anonymous namespace

extern "C" void kernel_launch(void* const* d_in, const int* in_sizes, int n_in,
                              void* d_out, int out_size)
{
    const float* input = (const float*)d_in[0];
    const float* eWih  = (const float*)d_in[1];
    const float* eWhh  = (const float*)d_in[2];
    const float* ebih  = (const float*)d_in[3];
    const float* ebhh  = (const float*)d_in[4];
    const float* dWih  = (const float*)d_in[5];
    const float* dWhh  = (const float*)d_in[6];
    const float* dbih  = (const float*)d_in[7];
    const float* dbhh  = (const float*)d_in[8];
    const float* fcW   = (const float*)d_in[9];
    const float* fcb   = (const float*)d_in[10];
    float* out = (float*)d_out;

    seq2seq_lstm_kernel<<<296, NT>>>(input, eWih, eWhh, ebih, ebhh,
                                     dWih, dWhh, dbih, dbhh, fcW, fcb, out);
}

// round 12
// speedup vs baseline: 1.7286x; 1.7286x over previous
#include <cuda_runtime.h>
#include <cstdint>

namespace {

constexpr int Tn = 512;
constexpr int Pn = 64;
constexpr int NB = 8;       // batch rows per CTA (= MMA N)
constexpr int NT = 256;
constexpr int KS = 14;      // k16 steps (K = 224: 72 hi*hi | 72 lo*hi | 72 hi*lo | 8 pad)
constexpr int BKS = 132;    // B_pair row stride in u32 words (== 4 mod 32)
constexpr int SAS = 260;    // sact row stride in floats   (== 4 mod 32)

__device__ __forceinline__ uint16_t f2bf(float x) {
    uint16_t r;
    asm("cvt.rn.bf16.f32 %0, %1;" : "=h"(r) : "f"(x));
    return r;
}
__device__ __forceinline__ float bf2f(uint16_t h) {
    return __uint_as_float((uint32_t)h << 16);
}
__device__ __forceinline__ float tanh_a(float x) {
    float y;
    asm("tanh.approx.f32 %0, %1;" : "=f"(y) : "f"(x));
    return y;
}
__device__ __forceinline__ float sig_a(float x) {
    return fmaf(tanh_a(0.5f * x), 0.5f, 0.5f);
}

// D += A*B  (m16n8k16, row.col, bf16 in, fp32 accum)
__device__ __forceinline__ void mma16816(float d[4], const uint32_t a[4],
                                         const uint32_t b[2]) {
    asm volatile(
        "mma.sync.aligned.m16n8k16.row.col.f32.bf16.bf16.f32 "
        "{%0,%1,%2,%3}, {%4,%5,%6,%7}, {%8,%9}, {%0,%1,%2,%3};"
        : "+f"(d[0]), "+f"(d[1]), "+f"(d[2]), "+f"(d[3])
        : "r"(a[0]), "r"(a[1]), "r"(a[2]), "r"(a[3]), "r"(b[0]), "r"(b[1]));
}

// A element for (gate row j, K col c) under the 3-term split layout.
__device__ __forceinline__ uint16_t elemA(
    const float* __restrict__ Whh, const float* __restrict__ Wih, int j, int c)
{
    if (c >= 216) return (uint16_t)0;
    const int kk = c % 72;
    const float w = (kk < 64) ? __ldg(Whh + j * 64 + kk)
                              : __ldg(Wih + j * 8 + (kk - 64));
    const uint16_t h = f2bf(w);
    if (c >= 72 && c < 144) return f2bf(w - bf2f(h));   // lo term
    return h;                                           // hi term
}

__device__ __forceinline__ uint32_t packA(
    const float* __restrict__ Whh, const float* __restrict__ Wih, int j, int c)
{
    return (uint32_t)elemA(Whh, Wih, j, c) |
           ((uint32_t)elemA(Whh, Wih, j, c + 1) << 16);
}

// Load this thread's A fragments (2 m-tiles x KS k-steps x 4 regs).
__device__ void loadA(uint32_t Af[2][KS][4],
                      const float* __restrict__ Whh, const float* __restrict__ Wih,
                      int wrp, int g, int tg)
{
#pragma unroll
    for (int tile = 0; tile < 2; tile++) {
        const int r0 = 16 * (2 * wrp + tile) + g;
#pragma unroll
        for (int ks = 0; ks < KS; ks++) {
            const int c0 = 16 * ks + 2 * tg;
            Af[tile][ks][0] = packA(Whh, Wih, r0,     c0);
            Af[tile][ks][1] = packA(Whh, Wih, r0 + 8, c0);
            Af[tile][ks][2] = packA(Whh, Wih, r0,     c0 + 8);
            Af[tile][ks][3] = packA(Whh, Wih, r0 + 8, c0 + 8);
        }
    }
}

// One gate GEMM step: 28 B-frag LDS + 28 HMMA + 8 STS to sact[n][m].
__device__ __forceinline__ void gemm_step(
    const uint32_t Af[2][KS][4], const uint32_t* __restrict__ Bp,
    float* __restrict__ sact, int wrp, int g, int tg)
{
    uint32_t bf[KS][2];
    const uint32_t* brow = Bp + g * BKS;     // g == n for B frags
#pragma unroll
    for (int ks = 0; ks < KS; ks++) {
        bf[ks][0] = brow[8 * ks + tg];       // k = 16ks+2tg, +1
        bf[ks][1] = brow[8 * ks + 4 + tg];   // k = 16ks+8+2tg, +1
    }
    float acc[2][2][4] = {};
#pragma unroll
    for (int ks = 0; ks < KS; ks++) {
        mma16816(acc[0][ks & 1], Af[0][ks], bf[ks]);
        mma16816(acc[1][ks & 1], Af[1][ks], bf[ks]);
    }
#pragma unroll
    for (int tile = 0; tile < 2; tile++) {
        const int m = 16 * (2 * wrp + tile) + g;
        const int base = (2 * tg) * SAS + m;     // sact[n=2tg][m]
        sact[base]           = acc[tile][0][0] + acc[tile][1][0];
        sact[base + SAS]     = acc[tile][0][1] + acc[tile][1][1];
        sact[base + 8]       = acc[tile][0][2] + acc[tile][1][2];
        sact[base + SAS + 8] = acc[tile][0][3] + acc[tile][1][3];
    }
}

// Activation: thread owns (batch n = warp, units u = 2l, 2l+1).
__device__ __forceinline__ void act_step(
    const float* __restrict__ sact, uint32_t* __restrict__ Bp,
    float* __restrict__ shf, const float bi[4][2],
    int n, int l, float& c0, float& c1, bool dec)
{
    const float* sr = sact + n * SAS + 2 * l;
    float2 gi = *(const float2*)(sr);
    float2 gf = *(const float2*)(sr + 64);
    float2 gg = *(const float2*)(sr + 128);
    float2 go = *(const float2*)(sr + 192);
    c0 = sig_a(gf.x + bi[1][0]) * c0 + sig_a(gi.x + bi[0][0]) * tanh_a(gg.x + bi[2][0]);
    c1 = sig_a(gf.y + bi[1][1]) * c1 + sig_a(gi.y + bi[0][1]) * tanh_a(gg.y + bi[2][1]);
    const float h0 = sig_a(go.x + bi[3][0]) * tanh_a(c0);
    const float h1 = sig_a(go.y + bi[3][1]) * tanh_a(c1);
    const uint16_t h0h = f2bf(h0), h1h = f2bf(h1);
    const uint32_t hw = (uint32_t)h0h | ((uint32_t)h1h << 16);
    const uint32_t lw = (uint32_t)f2bf(h0 - bf2f(h0h)) |
                        ((uint32_t)f2bf(h1 - bf2f(h1h)) << 16);
    uint32_t* br = Bp + n * BKS;
    br[l]      = hw;   // k = 2l,2l+1       (hi, term 1)
    br[36 + l] = hw;   // k = 72+2l..       (hi, term 2)
    br[72 + l] = lw;   // k = 144+2l..      (lo, term 3)
    if (dec) *(float2*)&shf[n * 68 + 2 * l] = make_float2(h0, h1);
}

// x split-store: u16 index == K index inside B_pair row.
__device__ __forceinline__ void store_x(uint32_t* __restrict__ Bp, int n, int f,
                                        float x)
{
    const uint16_t h  = f2bf(x);
    const uint16_t lo = f2bf(x - bf2f(h));
    uint16_t* row = (uint16_t*)(Bp + n * BKS);
    row[64 + f]  = h;
    row[136 + f] = h;
    row[208 + f] = lo;
}

__global__ void __launch_bounds__(NT, 1)
seq2seq_lstm_mma(
    const float* __restrict__ input,
    const float* __restrict__ eWih, const float* __restrict__ eWhh,
    const float* __restrict__ ebih, const float* __restrict__ ebhh,
    const float* __restrict__ dWih, const float* __restrict__ dWhh,
    const float* __restrict__ dbih, const float* __restrict__ dbhh,
    const float* __restrict__ fcW,  const float* __restrict__ fcb,
    float* __restrict__ out)
{
    __shared__ uint32_t Bp[NB * BKS];       // B pair-packed [n][k2]
    __shared__ float sact[NB * SAS];        // gates transposed [n][m]
    __shared__ float shf[NB * 68];          // fp32 h for decoder fc
    __shared__ float sfcw[8 * 64];
    __shared__ float sfcb[8];

    const int tid  = threadIdx.x;
    const int lane = tid & 31;
    const int wrp  = tid >> 5;
    const int g    = lane >> 2;     // mma group id
    const int tg   = lane & 3;      // thread-in-group
    const int b0   = blockIdx.x * NB;

    sfcw[tid]       = fcW[tid];
    sfcw[tid + NT]  = fcW[tid + NT];
    if (tid < 8) sfcb[tid] = fcb[tid];
    for (int i = tid; i < NB * BKS; i += NT) Bp[i] = 0;   // h(-1)=0 + pads

    uint32_t Af[2][KS][4];
    loadA(Af, eWhh, eWih, wrp, g, tg);

    float bi[4][2];
#pragma unroll
    for (int gt = 0; gt < 4; gt++) {
        bi[gt][0] = ebih[gt * 64 + 2 * lane]     + ebhh[gt * 64 + 2 * lane];
        bi[gt][1] = ebih[gt * 64 + 2 * lane + 1] + ebhh[gt * 64 + 2 * lane + 1];
    }

    const bool xth = tid < NB * 8;
    const int  xn  = tid >> 3, xf = tid & 7;
    const float* xptr = input + ((size_t)(b0 + xn) * Tn) * 8 + xf;
    float xreg = 0.0f;
    if (xth) {
        store_x(Bp, xn, xf, __ldg(xptr));    // x(0)
        xreg = __ldg(xptr + 8);              // x(1)
    }
    __syncthreads();

    float c0 = 0.0f, c1 = 0.0f;

    // ======================= encoder =======================
    for (int t = 0; t < Tn; t++) {
        gemm_step(Af, Bp, sact, wrp, g, tg);
        __syncthreads();    // sact ready; all B reads done

        act_step(sact, Bp, shf, bi, wrp, lane, c0, c1, false);
        if (xth && t + 1 < Tn) {
            store_x(Bp, xn, xf, xreg);
            if (t + 2 < Tn) xreg = __ldg(xptr + (size_t)(t + 2) * 8);
        }
        __syncthreads();    // B(t+1) ready
    }
    // B now holds h_enc(final) + x(T-1)

    // ---- decoder weights ----
    loadA(Af, dWhh, dWih, wrp, g, tg);
#pragma unroll
    for (int gt = 0; gt < 4; gt++) {
        bi[gt][0] = dbih[gt * 64 + 2 * lane]     + dbhh[gt * 64 + 2 * lane];
        bi[gt][1] = dbih[gt * 64 + 2 * lane + 1] + dbhh[gt * 64 + 2 * lane + 1];
    }

    // ======================= decoder =======================
    for (int p = 0; p < Pn; p++) {
        gemm_step(Af, Bp, sact, wrp, g, tg);
        __syncthreads();    // sact ready

        act_step(sact, Bp, shf, bi, wrp, lane, c0, c1, true);
        __syncthreads();    // h (B + shf) ready

        if (xth) {          // pred = h @ fcW^T + fcb ; also next x
            float a = sfcb[xf];
            const float4* hr = (const float4*)&shf[xn * 68];
            const float4* wr = (const float4*)&sfcw[xf * 64];
#pragma unroll
            for (int k = 0; k < 16; k++) {
                float4 hv = hr[k], wv = wr[k];
                a = fmaf(hv.x, wv.x, a);
                a = fmaf(hv.y, wv.y, a);
                a = fmaf(hv.z, wv.z, a);
                a = fmaf(hv.w, wv.w, a);
            }
            out[((size_t)(b0 + xn) * Pn + p) * 8 + xf] = a;
            store_x(Bp, xn, xf, a);
        }
        __syncthreads();    // x ready for next step
    }
}

} // anonymous namespace

extern "C" void kernel_launch(void* const* d_in, const int* in_sizes, int n_in,
                              void* d_out, int out_size)
{
    const float* input = (const float*)d_in[0];
    const float* eWih  = (const float*)d_in[1];
    const float* eWhh  = (const float*)d_in[2];
    const float* ebih  = (const float*)d_in[3];
    const float* ebhh  = (const float*)d_in[4];
    const float* dWih  = (const float*)d_in[5];
    const float* dWhh  = (const float*)d_in[6];
    const float* dbih  = (const float*)d_in[7];
    const float* dbhh  = (const float*)d_in[8];
    const float* fcW   = (const float*)d_in[9];
    const float* fcb   = (const float*)d_in[10];
    float* out = (float*)d_out;

    seq2seq_lstm_mma<<<1024 / NB, NT>>>(input, eWih, eWhh, ebih, ebhh,
                                        dWih, dWhh, dbih, dbhh, fcW, fcb, out);
}

// round 13
// speedup vs baseline: 1.7420x; 1.0077x over previous
#include <cuda_runtime.h>
#include <cstdint>

namespace {

constexpr int Tn = 512;
constexpr int Pn = 64;
constexpr int NB = 8;       // batch rows per CTA (= MMA N)
constexpr int NT = 256;
constexpr int KS = 14;      // k16 steps (K=224: 72 hi*hi | 72 lo*hi | 72 hi*lo | 8 pad)
constexpr int BKS = 132;    // B row stride in u32 words (== 4 mod 32)

__device__ __forceinline__ uint16_t f2bf(float x) {
    uint16_t r;
    asm("cvt.rn.bf16.f32 %0, %1;" : "=h"(r) : "f"(x));
    return r;
}
__device__ __forceinline__ float bf2f(uint16_t h) {
    return __uint_as_float((uint32_t)h << 16);
}
__device__ __forceinline__ float tanh_a(float x) {
    float y;
    asm("tanh.approx.f32 %0, %1;" : "=f"(y) : "f"(x));
    return y;
}
__device__ __forceinline__ float sig_a(float x) {
    return fmaf(tanh_a(0.5f * x), 0.5f, 0.5f);
}

__device__ __forceinline__ void mma16816(float d[4], const uint32_t a[4],
                                         const uint32_t b[2]) {
    asm volatile(
        "mma.sync.aligned.m16n8k16.row.col.f32.bf16.bf16.f32 "
        "{%0,%1,%2,%3}, {%4,%5,%6,%7}, {%8,%9}, {%0,%1,%2,%3};"
        : "+f"(d[0]), "+f"(d[1]), "+f"(d[2]), "+f"(d[3])
        : "r"(a[0]), "r"(a[1]), "r"(a[2]), "r"(a[3]), "r"(b[0]), "r"(b[1]));
}

// permuted A row m  ->  original gate row j = gate*64 + u
__device__ __forceinline__ int jrow(int m) {
    return (m & 3) * 64 + 4 * (m >> 4) + ((m >> 2) & 3);
}

__device__ __forceinline__ uint16_t elemA(
    const float* __restrict__ Whh, const float* __restrict__ Wih, int j, int c)
{
    if (c >= 216) return (uint16_t)0;
    const int kk = c % 72;
    const float w = (kk < 64) ? __ldg(Whh + j * 64 + kk)
                              : __ldg(Wih + j * 8 + (kk - 64));
    const uint16_t h = f2bf(w);
    if (c >= 72 && c < 144) return f2bf(w - bf2f(h));
    return h;
}
__device__ __forceinline__ uint32_t packA(
    const float* __restrict__ Whh, const float* __restrict__ Wih, int j, int c)
{
    return (uint32_t)elemA(Whh, Wih, j, c) |
           ((uint32_t)elemA(Whh, Wih, j, c + 1) << 16);
}

__device__ void loadA(uint32_t Af[2][KS][4],
                      const float* __restrict__ Whh, const float* __restrict__ Wih,
                      int wrp, int g, int tg)
{
#pragma unroll
    for (int tile = 0; tile < 2; tile++) {
        const int r0 = 16 * (2 * wrp + tile) + g;
#pragma unroll
        for (int ks = 0; ks < KS; ks++) {
            const int c0 = 16 * ks + 2 * tg;
            Af[tile][ks][0] = packA(Whh, Wih, jrow(r0),     c0);
            Af[tile][ks][1] = packA(Whh, Wih, jrow(r0 + 8), c0);
            Af[tile][ks][2] = packA(Whh, Wih, jrow(r0),     c0 + 8);
            Af[tile][ks][3] = packA(Whh, Wih, jrow(r0 + 8), c0 + 8);
        }
    }
}

// GEMM step: B frags, 28 HMMA, store D to this warp's sact region
// layout sw[gate][u_loc][n] with gate stride 72, u stride 8 (CF ST.64 / LDS.32)
__device__ __forceinline__ void gemm_step(
    const uint32_t Af[2][KS][4], const uint32_t* __restrict__ Bp,
    float* __restrict__ sw, int g, int tg)
{
    uint32_t bf[KS][2];
    const uint32_t* brow = Bp + g * BKS;
#pragma unroll
    for (int ks = 0; ks < KS; ks++) {
        bf[ks][0] = brow[8 * ks + tg];
        bf[ks][1] = brow[8 * ks + 4 + tg];
    }
    float acc[2][2][4] = {};
#pragma unroll
    for (int ks = 0; ks < KS; ks++) {
        mma16816(acc[0][ks & 1], Af[0][ks], bf[ks]);
        mma16816(acc[1][ks & 1], Af[1][ks], bf[ks]);
    }
    const int gate = g & 3;
#pragma unroll
    for (int tile = 0; tile < 2; tile++) {
        const int u00 = 4 * tile + (g >> 2);
        *(float2*)&sw[gate * 72 + u00 * 8 + 2 * tg] =
            make_float2(acc[tile][0][0] + acc[tile][1][0],
                        acc[tile][0][1] + acc[tile][1][1]);
        *(float2*)&sw[gate * 72 + (u00 + 2) * 8 + 2 * tg] =
            make_float2(acc[tile][0][2] + acc[tile][1][2],
                        acc[tile][0][3] + acc[tile][1][3]);
    }
}

// Activation for (n, gu) -> h written to Bnext (split bf16), optionally shf.
__device__ __forceinline__ void act_one(
    const float* __restrict__ sw, uint32_t* __restrict__ Bnext,
    float* __restrict__ shf, const float* bi4,
    int n, int uloc, int gu, float& c, bool dec)
{
    const float gi = sw[0 * 72 + uloc * 8 + n] + bi4[0];
    const float gf = sw[1 * 72 + uloc * 8 + n] + bi4[1];
    const float gg = sw[2 * 72 + uloc * 8 + n] + bi4[2];
    const float go = sw[3 * 72 + uloc * 8 + n] + bi4[3];
    c = sig_a(gf) * c + sig_a(gi) * tanh_a(gg);
    const float h = sig_a(go) * tanh_a(c);
    const uint16_t hh = f2bf(h);
    const uint16_t hl = f2bf(h - bf2f(hh));
    uint16_t* row = (uint16_t*)(Bnext + n * BKS);
    row[gu]       = hh;
    row[72 + gu]  = hh;
    row[144 + gu] = hl;
    if (dec) shf[n * 68 + gu] = h;
}

__device__ __forceinline__ void store_x(uint32_t* __restrict__ Bp, int n, int f,
                                        float x)
{
    const uint16_t h  = f2bf(x);
    const uint16_t lo = f2bf(x - bf2f(h));
    uint16_t* row = (uint16_t*)(Bp + n * BKS);
    row[64 + f]  = h;
    row[136 + f] = h;
    row[208 + f] = lo;
}

__global__ void __launch_bounds__(NT, 1)
seq2seq_lstm_mma(
    const float* __restrict__ input,
    const float* __restrict__ eWih, const float* __restrict__ eWhh,
    const float* __restrict__ ebih, const float* __restrict__ ebhh,
    const float* __restrict__ dWih, const float* __restrict__ dWhh,
    const float* __restrict__ dbih, const float* __restrict__ dbhh,
    const float* __restrict__ fcW,  const float* __restrict__ fcb,
    float* __restrict__ out)
{
    __shared__ uint32_t Bp[2][NB * BKS];   // double-buffered B [parity][n][k2]
    __shared__ float sact[8 * 288];        // per-warp D regions
    __shared__ float shf[NB * 68];         // fp32 h for decoder fc
    __shared__ float sfcw[8 * 64];
    __shared__ float sfcb[8];

    const int tid  = threadIdx.x;
    const int lane = tid & 31;
    const int wrp  = tid >> 5;
    const int g    = lane >> 2;
    const int tg   = lane & 3;
    const int b0   = blockIdx.x * NB;

    float* sw = sact + wrp * 288;

    // activation role: (n, u pair)
    const int an   = lane & 7;
    const int ul0  = lane >> 3;            // local units ul0, ul0+4
    const int gu0  = 8 * wrp + ul0;
    const int gu1  = gu0 + 4;

    sfcw[tid]      = fcW[tid];
    sfcw[tid + NT] = fcW[tid + NT];
    if (tid < 8) sfcb[tid] = fcb[tid];
    for (int i = tid; i < 2 * NB * BKS; i += NT) ((uint32_t*)Bp)[i] = 0;

    uint32_t Af[2][KS][4];
    loadA(Af, eWhh, eWih, wrp, g, tg);

    float bi0[4], bi1[4];
#pragma unroll
    for (int gt = 0; gt < 4; gt++) {
        bi0[gt] = ebih[gt * 64 + gu0] + ebhh[gt * 64 + gu0];
        bi1[gt] = ebih[gt * 64 + gu1] + ebhh[gt * 64 + gu1];
    }

    const bool xth = tid < NB * 8;
    const int  xn  = tid >> 3, xf = tid & 7;
    const float* xptr = input + ((size_t)(b0 + xn) * Tn) * 8 + xf;
    float xreg = 0.0f, xlast = 0.0f;
    if (xth) {
        xlast = __ldg(xptr);
        store_x(Bp[0], xn, xf, xlast);       // x(0)
        xreg = __ldg(xptr + 8);              // x(1)
    }
    __syncthreads();

    float c0 = 0.0f, c1 = 0.0f;

    // ================= encoder: 1 CTA barrier / step =================
    for (int t = 0; t < Tn; t++) {
        gemm_step(Af, Bp[t & 1], sw, g, tg);
        float xpre = (xth && t + 2 < Tn) ? __ldg(xptr + (size_t)(t + 2) * 8) : 0.0f;
        __syncwarp();

        uint32_t* Bn = Bp[(t + 1) & 1];
        act_one(sw, Bn, shf, bi0, an, ul0,     gu0, c0, false);
        act_one(sw, Bn, shf, bi1, an, ul0 + 4, gu1, c1, false);
        if (xth) {
            const float xs = (t + 1 < Tn) ? xreg : xlast;   // replay x_last at end
            store_x(Bn, xn, xf, xs);
            xlast = xs;
            xreg  = xpre;
        }
        __syncthreads();
    }
    // B[0] holds h_enc(final) + x(T-1)

    // ---- decoder weights ----
    loadA(Af, dWhh, dWih, wrp, g, tg);
#pragma unroll
    for (int gt = 0; gt < 4; gt++) {
        bi0[gt] = dbih[gt * 64 + gu0] + dbhh[gt * 64 + gu0];
        bi1[gt] = dbih[gt * 64 + gu1] + dbhh[gt * 64 + gu1];
    }

    // ================= decoder =================
    for (int p = 0; p < Pn; p++) {
        const int pr = p & 1;
        gemm_step(Af, Bp[pr], sw, g, tg);
        __syncwarp();

        uint32_t* Bn = Bp[pr ^ 1];
        act_one(sw, Bn, shf, bi0, an, ul0,     gu0, c0, true);
        act_one(sw, Bn, shf, bi1, an, ul0 + 4, gu1, c1, true);
        __syncthreads();   // h (B + shf) ready

        if (xth) {         // pred = h @ fcW^T + fcb ; also next x
            float a = sfcb[xf];
            const float4* hr = (const float4*)&shf[xn * 68];
            const float4* wr = (const float4*)&sfcw[xf * 64];
#pragma unroll
            for (int k = 0; k < 16; k++) {
                float4 hv = hr[k], wv = wr[k];
                a = fmaf(hv.x, wv.x, a);
                a = fmaf(hv.y, wv.y, a);
                a = fmaf(hv.z, wv.z, a);
                a = fmaf(hv.w, wv.w, a);
            }
            out[((size_t)(b0 + xn) * Pn + p) * 8 + xf] = a;
            store_x(Bn, xn, xf, a);
        }
        __syncthreads();   // x ready for next step
    }
}

} // anonymous namespace

extern "C" void kernel_launch(void* const* d_in, const int* in_sizes, int n_in,
                              void* d_out, int out_size)
{
    const float* input = (const float*)d_in[0];
    const float* eWih  = (const float*)d_in[1];
    const float* eWhh  = (const float*)d_in[2];
    const float* ebih  = (const float*)d_in[3];
    const float* ebhh  = (const float*)d_in[4];
    const float* dWih  = (const float*)d_in[5];
    const float* dWhh  = (const float*)d_in[6];
    const float* dbih  = (const float*)d_in[7];
    const float* dbhh  = (const float*)d_in[8];
    const float* fcW   = (const float*)d_in[9];
    const float* fcb   = (const float*)d_in[10];
    float* out = (float*)d_out;

    seq2seq_lstm_mma<<<1024 / NB, NT>>>(input, eWih, eWhh, ebih, ebhh,
                                        dWih, dWhh, dbih, dbhh, fcW, fcb, out);
}